// round 1
// baseline (speedup 1.0000x reference)
#include <cuda_runtime.h>

// Problem constants (fixed by the dataset)
#define G_   1024
#define N_   65536
#define D_   128
#define E_   400000

// Scratch (device globals — no allocations allowed)
__device__ __align__(16) float g_A[G_ * 128];      // graph_and_focus @ W1[0:384] + b1   (combined 64 scorer + 64 type cols)
__device__ __align__(16) float g_B[N_ * 128];      // node_reps @ W1[384:512]            (32 MB)
__device__ __align__(16) float g_distC[10 * 128];  // dist_table[d] * W1[512]
__device__ float g_cstop[64];                      // no_more_edges_rep @ scorer_W1[384:516]

// ---------------------------------------------------------------------------
// kP: tiny precomputes (distC table, stop-row constant)
// ---------------------------------------------------------------------------
__global__ void kP(const float* __restrict__ dist_table, const float* __restrict__ no_more,
                   const float* __restrict__ sW1, const float* __restrict__ tW1) {
    int j = threadIdx.x;  // 128 threads
    float wj = (j < 64) ? sW1[512 * 64 + j] : tW1[512 * 64 + (j - 64)];
#pragma unroll
    for (int d = 0; d < 10; d++) g_distC[d * 128 + j] = dist_table[d] * wj;
    if (j < 64) {
        float s = 0.f;
#pragma unroll 4
        for (int k = 0; k < 132; k++) s += no_more[k] * sW1[(384 + k) * 64 + j];
        g_cstop[j] = s;
    }
}

// ---------------------------------------------------------------------------
// kA: per-graph A[g][j] = [imr|pgr|focus] @ W1[0:384] + b1 ; also stop logits
//     grid 128 blocks x 128 threads, 8 graphs per block
// ---------------------------------------------------------------------------
__global__ void kA(const float* __restrict__ imr, const float* __restrict__ pgr,
                   const float* __restrict__ nodes, const int* __restrict__ focus,
                   const float* __restrict__ sW1, const float* __restrict__ sb1,
                   const float* __restrict__ tW1, const float* __restrict__ tb1,
                   const float* __restrict__ sW2, const float* __restrict__ sb2,
                   float* __restrict__ out) {
    __shared__ float xs[8][384];
    __shared__ float sred[8][2];
    int j = threadIdx.x;         // 0..127 = combined hidden col
    int g0 = blockIdx.x * 8;
#pragma unroll
    for (int r = 0; r < 8; r++) {
        int g = g0 + r;
        xs[r][j]       = imr[g * 128 + j];
        xs[r][128 + j] = pgr[g * 128 + j];
        xs[r][256 + j] = nodes[focus[g] * 128 + j];
    }
    __syncthreads();
    bool isS = (j < 64);
    float bias = isS ? sb1[j] : tb1[j - 64];
    const float* W = isS ? (sW1 + j) : (tW1 + (j - 64));
    float acc[8];
#pragma unroll
    for (int r = 0; r < 8; r++) acc[r] = bias;
#pragma unroll 4
    for (int k = 0; k < 384; k++) {
        float w = W[k * 64];
#pragma unroll
        for (int r = 0; r < 8; r++) acc[r] = fmaf(xs[r][k], w, acc[r]);
    }
#pragma unroll
    for (int r = 0; r < 8; r++) g_A[(g0 + r) * 128 + j] = acc[r];

    // Stop logits: h = relu(acc + cstop) (scorer half only), dot with scorer_W2
    float ws2 = isS ? sW2[j] : 0.f;
    float cst = isS ? g_cstop[j] : 0.f;
#pragma unroll
    for (int r = 0; r < 8; r++) {
        float pv = isS ? fmaxf(acc[r] + cst, 0.f) * ws2 : 0.f;
#pragma unroll
        for (int o = 16; o >= 1; o >>= 1) pv += __shfl_xor_sync(0xffffffffu, pv, o);
        if ((j & 31) == 0 && isS) sred[r][j >> 5] = pv;
    }
    __syncthreads();
    if (j < 8) out[E_ + g0 + j] = sred[j][0] + sred[j][1] + sb2[0];
}

// ---------------------------------------------------------------------------
// kB: B[n][pass*64 + j] = node_reps[n] @ W1pass[384:512]
//     grid (N/64, 2) blocks x 256 threads. smem: W tile 32KB + x tile 8KB (<48KB)
//     64 rows per block, processed in 4 chunks of 16 rows; thread = (col j, 4 rows)
// ---------------------------------------------------------------------------
__global__ void kB(const float* __restrict__ nodes, const float* __restrict__ sW1,
                   const float* __restrict__ tW1) {
    __shared__ float sW[128 * 64];   // [k][j]
    __shared__ float xs[16 * 128];   // [r][k]
    int tid = threadIdx.x;           // 256
    int j  = tid & 63;
    int rh = tid >> 6;               // 0..3 -> rows rh*4 .. rh*4+3 of each 16-chunk
    int pass = blockIdx.y;           // 0 = scorer cols, 1 = type cols
    const float* W1 = pass ? tW1 : sW1;
    for (int idx = tid; idx < 128 * 64; idx += 256) {
        int k = idx >> 6, jj = idx & 63;
        sW[idx] = W1[(384 + k) * 64 + jj];
    }
    int row0 = blockIdx.x * 64;
    for (int c = 0; c < 4; c++) {
        __syncthreads();
        int r0 = row0 + c * 16;
        for (int idx = tid; idx < 16 * 128; idx += 256)
            xs[idx] = nodes[r0 * 128 + idx];
        __syncthreads();
        float acc0 = 0.f, acc1 = 0.f, acc2 = 0.f, acc3 = 0.f;
        const float* x0 = xs + (rh * 4) * 128;
#pragma unroll 8
        for (int k = 0; k < 128; k += 4) {
            float4 xa = *(const float4*)(x0 + k);
            float4 xb = *(const float4*)(x0 + 128 + k);
            float4 xc = *(const float4*)(x0 + 256 + k);
            float4 xd = *(const float4*)(x0 + 384 + k);
            float w0 = sW[(k + 0) * 64 + j];
            float w1 = sW[(k + 1) * 64 + j];
            float w2 = sW[(k + 2) * 64 + j];
            float w3 = sW[(k + 3) * 64 + j];
            acc0 = fmaf(xa.w, w3, fmaf(xa.z, w2, fmaf(xa.y, w1, fmaf(xa.x, w0, acc0))));
            acc1 = fmaf(xb.w, w3, fmaf(xb.z, w2, fmaf(xb.y, w1, fmaf(xb.x, w0, acc1))));
            acc2 = fmaf(xc.w, w3, fmaf(xc.z, w2, fmaf(xc.y, w1, fmaf(xc.x, w0, acc2))));
            acc3 = fmaf(xd.w, w3, fmaf(xd.z, w2, fmaf(xd.y, w1, fmaf(xd.x, w0, acc3))));
        }
        float* o = g_B + (r0 + rh * 4) * 128 + pass * 64 + j;
        o[0] = acc0; o[128] = acc1; o[256] = acc2; o[384] = acc3;
    }
}

// ---------------------------------------------------------------------------
// kE: per-edge assembly + second layers. One warp per edge (grid-stride).
//     lane owns 4 combined-hidden cols (lanes 0-15 scorer, 16-31 type).
// ---------------------------------------------------------------------------
__global__ void kE(const int* __restrict__ targets, const int* __restrict__ n2g,
                   const float4* __restrict__ feats4,
                   const float* __restrict__ sW1, const float* __restrict__ tW1,
                   const float* __restrict__ sW2, const float* __restrict__ sb2,
                   const float* __restrict__ tW2, const float* __restrict__ tb2,
                   float* __restrict__ out) {
    int lane = threadIdx.x & 31;
    int gw = (blockIdx.x * blockDim.x + threadIdx.x) >> 5;
    int nw = (gridDim.x * blockDim.x) >> 5;
    bool isS = (lane < 16);
    int cbase = isS ? 4 * lane : 4 * (lane - 16);
    const float* W1 = isS ? sW1 : tW1;
    float4 w513 = *(const float4*)(W1 + 513 * 64 + cbase);
    float4 w514 = *(const float4*)(W1 + 514 * 64 + cbase);
    float4 w515 = *(const float4*)(W1 + 515 * 64 + cbase);
    float4 ws2 = make_float4(0.f, 0.f, 0.f, 0.f);
    float tw[4][3];
#pragma unroll
    for (int q = 0; q < 4; q++) { tw[q][0] = tw[q][1] = tw[q][2] = 0.f; }
    if (isS) {
        ws2 = *(const float4*)(sW2 + cbase);
    } else {
#pragma unroll
        for (int q = 0; q < 4; q++) {
            tw[q][0] = tW2[(cbase + q) * 3 + 0];
            tw[q][1] = tW2[(cbase + q) * 3 + 1];
            tw[q][2] = tW2[(cbase + q) * 3 + 2];
        }
    }
    float sb2v = sb2[0];
    float tb0 = tb2[0], tb1v = tb2[1], tb2v = tb2[2];
    const float4* A4  = (const float4*)g_A;
    const float4* B4  = (const float4*)g_B;
    const float4* DC4 = (const float4*)g_distC;
    float* outT = out + (E_ + G_);

    for (int e = gw; e < E_; e += nw) {
        int t = targets[e];
        int g = n2g[t];
        float4 f = feats4[e];
        int d = (int)fminf(f.x, 9.0f);
        float4 a  = A4[g * 32 + lane];
        float4 b  = B4[t * 32 + lane];
        float4 dc = DC4[d * 32 + lane];
        float hx = fmaxf(fmaf(f.y, w513.x, fmaf(f.z, w514.x, fmaf(f.w, w515.x, a.x + b.x + dc.x))), 0.f);
        float hy = fmaxf(fmaf(f.y, w513.y, fmaf(f.z, w514.y, fmaf(f.w, w515.y, a.y + b.y + dc.y))), 0.f);
        float hz = fmaxf(fmaf(f.y, w513.z, fmaf(f.z, w514.z, fmaf(f.w, w515.z, a.z + b.z + dc.z))), 0.f);
        float hw = fmaxf(fmaf(f.y, w513.w, fmaf(f.z, w514.w, fmaf(f.w, w515.w, a.w + b.w + dc.w))), 0.f);
        float v0, v1, v2;
        if (isS) {
            v0 = fmaf(hx, ws2.x, fmaf(hy, ws2.y, fmaf(hz, ws2.z, hw * ws2.w)));
            v1 = 0.f; v2 = 0.f;
        } else {
            v0 = fmaf(hx, tw[0][0], fmaf(hy, tw[1][0], fmaf(hz, tw[2][0], hw * tw[3][0])));
            v1 = fmaf(hx, tw[0][1], fmaf(hy, tw[1][1], fmaf(hz, tw[2][1], hw * tw[3][1])));
            v2 = fmaf(hx, tw[0][2], fmaf(hy, tw[1][2], fmaf(hz, tw[2][2], hw * tw[3][2])));
        }
        // 16-lane segmented butterfly (groups [0,16) and [16,32) stay closed)
#pragma unroll
        for (int o = 1; o <= 8; o <<= 1) {
            v0 += __shfl_xor_sync(0xffffffffu, v0, o);
            v1 += __shfl_xor_sync(0xffffffffu, v1, o);
            v2 += __shfl_xor_sync(0xffffffffu, v2, o);
        }
        if (lane == 0) out[e] = v0 + sb2v;
        if (lane == 16) {
            outT[3 * e]     = v0 + tb0;
            outT[3 * e + 1] = v1 + tb1v;
            outT[3 * e + 2] = v2 + tb2v;
        }
    }
}

// ---------------------------------------------------------------------------
extern "C" void kernel_launch(void* const* d_in, const int* in_sizes, int n_in,
                              void* d_out, int out_size) {
    const float* imr     = (const float*)d_in[0];
    const float* pgr     = (const float*)d_in[1];
    const float* nodes   = (const float*)d_in[2];
    const int*   focus   = (const int*)d_in[3];
    const int*   n2g     = (const int*)d_in[4];
    const int*   targets = (const int*)d_in[5];
    const float* feats   = (const float*)d_in[6];
    int p = 7;
    if (p < n_in && in_sizes[p] == 1) p++;  // skip num_graphs_in_batch scalar if present
    const float* dist_table = (const float*)d_in[p++];  // [10]
    const float* no_more    = (const float*)d_in[p++];  // [132]
    const float* sW1 = (const float*)d_in[p++];         // [516,64]
    const float* sb1 = (const float*)d_in[p++];         // [64]
    const float* sW2 = (const float*)d_in[p++];         // [64]
    const float* sb2 = (const float*)d_in[p++];         // [1]
    const float* tW1 = (const float*)d_in[p++];         // [516,64]
    const float* tb1 = (const float*)d_in[p++];         // [64]
    const float* tW2 = (const float*)d_in[p++];         // [64,3]
    const float* tb2 = (const float*)d_in[p++];         // [3]
    float* out = (float*)d_out;

    kP<<<1, 128>>>(dist_table, no_more, sW1, tW1);
    kA<<<G_ / 8, 128>>>(imr, pgr, nodes, focus, sW1, sb1, tW1, tb1, sW2, sb2, out);
    kB<<<dim3(N_ / 64, 2), 256>>>(nodes, sW1, tW1);
    kE<<<1184, 256>>>(targets, n2g, (const float4*)feats, sW1, tW1, sW2, sb2, tW2, tb2, out);
}

// round 2
// speedup vs baseline: 1.2714x; 1.2714x over previous
#include <cuda_runtime.h>

#define G_   1024
#define N_   65536
#define D_   128
#define E_   400000

// Scratch (device globals — no allocations allowed)
__device__ __align__(16) float g_A[G_ * 128];      // graph_and_focus @ W1[0:384] + b1 (64 scorer | 64 type cols)
__device__ __align__(16) float g_C[N_ * 128];      // node @ W1[384:512] + A[n2g[node]]  (fused per-node table, 32MB)
__device__ __align__(16) float g_distC[10 * 128];  // dist_table[d] * W1[512]
__device__ float g_cstop[64];                      // no_more_edges_rep @ scorer_W1[384:516]

// packed f32x2 fma (full-rate FMA pipe on Blackwell; 3-reg FFMA is half-rate)
__device__ __forceinline__ unsigned long long fma2(unsigned long long a, unsigned long long b,
                                                   unsigned long long c) {
    unsigned long long d;
    asm("fma.rn.f32x2 %0, %1, %2, %3;" : "=l"(d) : "l"(a), "l"(b), "l"(c));
    return d;
}
__device__ __forceinline__ unsigned long long pack2(float lo, float hi) {
    unsigned long long d;
    asm("mov.b64 %0, {%1, %2};" : "=l"(d) : "f"(lo), "f"(hi));
    return d;
}
__device__ __forceinline__ void unpack2(unsigned long long v, float& lo, float& hi) {
    asm("mov.b64 {%0, %1}, %2;" : "=f"(lo), "=f"(hi) : "l"(v));
}

// ---------------------------------------------------------------------------
// kP: tiny precomputes (distC table, stop-row constant)
// ---------------------------------------------------------------------------
__global__ void kP(const float* __restrict__ dist_table, const float* __restrict__ no_more,
                   const float* __restrict__ sW1, const float* __restrict__ tW1) {
    int j = threadIdx.x;  // 128 threads
    float wj = (j < 64) ? sW1[512 * 64 + j] : tW1[512 * 64 + (j - 64)];
#pragma unroll
    for (int d = 0; d < 10; d++) g_distC[d * 128 + j] = dist_table[d] * wj;
    if (j < 64) {
        float s = 0.f;
#pragma unroll 4
        for (int k = 0; k < 132; k++) s += no_more[k] * sW1[(384 + k) * 64 + j];
        g_cstop[j] = s;
    }
}

// ---------------------------------------------------------------------------
// kA: per-graph A[g][j] = [imr|pgr|focus] @ W1[0:384] + b1 ; also stop logits
// ---------------------------------------------------------------------------
__global__ void kA(const float* __restrict__ imr, const float* __restrict__ pgr,
                   const float* __restrict__ nodes, const int* __restrict__ focus,
                   const float* __restrict__ sW1, const float* __restrict__ sb1,
                   const float* __restrict__ tW1, const float* __restrict__ tb1,
                   const float* __restrict__ sW2, const float* __restrict__ sb2,
                   float* __restrict__ out) {
    __shared__ float xs[8][384];
    __shared__ float sred[8][2];
    int j = threadIdx.x;         // 0..127 = combined hidden col
    int g0 = blockIdx.x * 8;
#pragma unroll
    for (int r = 0; r < 8; r++) {
        int g = g0 + r;
        xs[r][j]       = imr[g * 128 + j];
        xs[r][128 + j] = pgr[g * 128 + j];
        xs[r][256 + j] = nodes[focus[g] * 128 + j];
    }
    __syncthreads();
    bool isS = (j < 64);
    float bias = isS ? sb1[j] : tb1[j - 64];
    const float* W = isS ? (sW1 + j) : (tW1 + (j - 64));
    float acc[8];
#pragma unroll
    for (int r = 0; r < 8; r++) acc[r] = bias;
#pragma unroll 4
    for (int k = 0; k < 384; k++) {
        float w = W[k * 64];
#pragma unroll
        for (int r = 0; r < 8; r++) acc[r] = fmaf(xs[r][k], w, acc[r]);
    }
#pragma unroll
    for (int r = 0; r < 8; r++) g_A[(g0 + r) * 128 + j] = acc[r];

    float ws2 = isS ? sW2[j] : 0.f;
    float cst = isS ? g_cstop[j] : 0.f;
#pragma unroll
    for (int r = 0; r < 8; r++) {
        float pv = isS ? fmaxf(acc[r] + cst, 0.f) * ws2 : 0.f;
#pragma unroll
        for (int o = 16; o >= 1; o >>= 1) pv += __shfl_xor_sync(0xffffffffu, pv, o);
        if ((j & 31) == 0 && isS) sred[r][j >> 5] = pv;
    }
    __syncthreads();
    if (j < 8) out[E_ + g0 + j] = sred[j][0] + sred[j][1] + sb2[0];
}

// ---------------------------------------------------------------------------
// kB: C[n][j] = node_reps[n] @ W1combined[384:512] + A[n2g[n]][j]
//     512 blocks x 256 threads. Block tile 128 rows x 128 cols, thread 8x8,
//     packed f32x2 FMA (row pairs). smem ~33KB.
// ---------------------------------------------------------------------------
__global__ __launch_bounds__(256) void kB(const float* __restrict__ nodes,
                                          const float* __restrict__ sW1,
                                          const float* __restrict__ tW1,
                                          const int* __restrict__ n2g) {
    __shared__ float xs[32][132];   // [k][r] transposed, padded
    __shared__ float sw[32][128];   // [k][j] combined cols
    int tid = threadIdx.x;
    int tx = tid & 15, ty = tid >> 4;
    int c0 = tx * 8, r0 = ty * 8;
    int row0 = blockIdx.x * 128;

    unsigned long long acc[4][8];   // [row-pair][col]: rows (r0+2i, r0+2i+1)
#pragma unroll
    for (int i = 0; i < 4; i++)
#pragma unroll
        for (int j = 0; j < 8; j++) acc[i][j] = 0ull;

    for (int kc = 0; kc < 128; kc += 32) {
        // stage W chunk [32k x 128j]
        for (int i = tid; i < 32 * 128; i += 256) {
            int k = i >> 7, j = i & 127;
            sw[k][j] = (j < 64) ? sW1[(384 + kc + k) * 64 + j]
                                : tW1[(384 + kc + k) * 64 + (j - 64)];
        }
        // stage x chunk transposed [32k x 128r]
        for (int f = tid; f < 1024; f += 256) {
            int r = f >> 3, kq = (f & 7) << 2;
            float4 v = *(const float4*)(nodes + (size_t)(row0 + r) * 128 + kc + kq);
            xs[kq + 0][r] = v.x; xs[kq + 1][r] = v.y;
            xs[kq + 2][r] = v.z; xs[kq + 3][r] = v.w;
        }
        __syncthreads();
#pragma unroll 8
        for (int k = 0; k < 32; k++) {
            const unsigned long long* xp = (const unsigned long long*)&xs[k][r0];
            unsigned long long x0 = xp[0], x1 = xp[1], x2 = xp[2], x3 = xp[3];
            float4 wa = *(const float4*)&sw[k][c0];
            float4 wb = *(const float4*)&sw[k][c0 + 4];
            unsigned long long wd[8];
            wd[0] = pack2(wa.x, wa.x); wd[1] = pack2(wa.y, wa.y);
            wd[2] = pack2(wa.z, wa.z); wd[3] = pack2(wa.w, wa.w);
            wd[4] = pack2(wb.x, wb.x); wd[5] = pack2(wb.y, wb.y);
            wd[6] = pack2(wb.z, wb.z); wd[7] = pack2(wb.w, wb.w);
#pragma unroll
            for (int j = 0; j < 8; j++) {
                acc[0][j] = fma2(x0, wd[j], acc[0][j]);
                acc[1][j] = fma2(x1, wd[j], acc[1][j]);
                acc[2][j] = fma2(x2, wd[j], acc[2][j]);
                acc[3][j] = fma2(x3, wd[j], acc[3][j]);
            }
        }
        __syncthreads();
    }
    // epilogue: unpack, add A[n2g[row]] (n2g sorted -> near-sequential gather), store
#pragma unroll
    for (int i = 0; i < 4; i++) {
        float lo[8], hi[8];
#pragma unroll
        for (int j = 0; j < 8; j++) unpack2(acc[i][j], lo[j], hi[j]);
        int rowA = row0 + r0 + 2 * i;
        int gA = n2g[rowA], gB = n2g[rowA + 1];
        const float4* Aa = (const float4*)(g_A + (size_t)gA * 128 + c0);
        const float4* Ab = (const float4*)(g_A + (size_t)gB * 128 + c0);
        float4 a0 = Aa[0], a1 = Aa[1], b0 = Ab[0], b1 = Ab[1];
        float4 s;
        float* o0 = g_C + (size_t)rowA * 128 + c0;
        float* o1 = o0 + 128;
        s = make_float4(lo[0] + a0.x, lo[1] + a0.y, lo[2] + a0.z, lo[3] + a0.w);
        *(float4*)(o0) = s;
        s = make_float4(lo[4] + a1.x, lo[5] + a1.y, lo[6] + a1.z, lo[7] + a1.w);
        *(float4*)(o0 + 4) = s;
        s = make_float4(hi[0] + b0.x, hi[1] + b0.y, hi[2] + b0.z, hi[3] + b0.w);
        *(float4*)(o1) = s;
        s = make_float4(hi[4] + b1.x, hi[5] + b1.y, hi[6] + b1.z, hi[7] + b1.w);
        *(float4*)(o1 + 4) = s;
    }
}

// ---------------------------------------------------------------------------
// kE: per-edge: single gather C[t] + distC + feature FMAs + tiny layer-2.
//     One warp per edge; lanes 0-15 scorer cols, 16-31 type cols (4 cols/lane).
//     9-shuffle dual butterfly carries all 4 output sums.
// ---------------------------------------------------------------------------
__global__ __launch_bounds__(256) void kE(const int* __restrict__ targets,
                   const float4* __restrict__ feats4,
                   const float* __restrict__ sW1, const float* __restrict__ tW1,
                   const float* __restrict__ sW2, const float* __restrict__ sb2,
                   const float* __restrict__ tW2, const float* __restrict__ tb2,
                   float* __restrict__ out) {
    int lane = threadIdx.x & 31;
    int gw = (blockIdx.x * blockDim.x + threadIdx.x) >> 5;
    int nw = (gridDim.x * blockDim.x) >> 5;
    bool isS = (lane < 16);
    int cbase = isS ? 4 * lane : 4 * (lane - 16);
    const float* W1 = isS ? sW1 : tW1;
    float4 w513 = *(const float4*)(W1 + 513 * 64 + cbase);
    float4 w514 = *(const float4*)(W1 + 514 * 64 + cbase);
    float4 w515 = *(const float4*)(W1 + 515 * 64 + cbase);
    float4 ws2 = make_float4(0.f, 0.f, 0.f, 0.f);
    float tw[4][3];
#pragma unroll
    for (int q = 0; q < 4; q++) { tw[q][0] = tw[q][1] = tw[q][2] = 0.f; }
    if (isS) {
        ws2 = *(const float4*)(sW2 + cbase);
    } else {
#pragma unroll
        for (int q = 0; q < 4; q++) {
            tw[q][0] = tW2[(cbase + q) * 3 + 0];
            tw[q][1] = tW2[(cbase + q) * 3 + 1];
            tw[q][2] = tW2[(cbase + q) * 3 + 2];
        }
    }
    float sb2v = sb2[0];
    float tb0 = tb2[0], tb1v = tb2[1], tb2v = tb2[2];
    const float4* C4  = (const float4*)g_C;
    const float4* DC4 = (const float4*)g_distC;
    float* outT = out + (E_ + G_);

    for (int e = gw; e < E_; e += nw) {
        int t = targets[e];
        float4 f = feats4[e];
        float4 c = C4[(size_t)t * 32 + lane];
        int d = (int)fminf(f.x, 9.0f);
        float4 dc = DC4[d * 32 + lane];
        float hx = fmaxf(fmaf(f.y, w513.x, fmaf(f.z, w514.x, fmaf(f.w, w515.x, c.x + dc.x))), 0.f);
        float hy = fmaxf(fmaf(f.y, w513.y, fmaf(f.z, w514.y, fmaf(f.w, w515.y, c.y + dc.y))), 0.f);
        float hz = fmaxf(fmaf(f.y, w513.z, fmaf(f.z, w514.z, fmaf(f.w, w515.z, c.z + dc.z))), 0.f);
        float hw = fmaxf(fmaf(f.y, w513.w, fmaf(f.z, w514.w, fmaf(f.w, w515.w, c.w + dc.w))), 0.f);
        float v0, v1, v2;
        if (isS) {
            v0 = fmaf(hx, ws2.x, fmaf(hy, ws2.y, fmaf(hz, ws2.z, hw * ws2.w)));
            v1 = 0.f; v2 = 0.f;
        } else {
            v0 = fmaf(hx, tw[0][0], fmaf(hy, tw[1][0], fmaf(hz, tw[2][0], hw * tw[3][0])));
            v1 = fmaf(hx, tw[0][1], fmaf(hy, tw[1][1], fmaf(hz, tw[2][1], hw * tw[3][1])));
            v2 = fmaf(hx, tw[0][2], fmaf(hy, tw[1][2], fmaf(hz, tw[2][2], hw * tw[3][2])));
        }
        // dual 16-lane butterfly: p carries {scorer v0 | type v1}, q carries {type v0 | type v2}
        float p = isS ? v0 : v1;
        float q = __shfl_xor_sync(0xffffffffu, v0, 16);
        q = isS ? q : v2;
#pragma unroll
        for (int o = 1; o <= 8; o <<= 1) {
            p += __shfl_xor_sync(0xffffffffu, p, o);
            q += __shfl_xor_sync(0xffffffffu, q, o);
        }
        if (lane == 0) {
            out[e] = p + sb2v;          // scorer logit
            outT[3 * e] = q + tb0;      // type logit 0
        }
        if (lane == 16) {
            outT[3 * e + 1] = p + tb1v; // type logit 1
            outT[3 * e + 2] = q + tb2v; // type logit 2
        }
    }
}

// ---------------------------------------------------------------------------
extern "C" void kernel_launch(void* const* d_in, const int* in_sizes, int n_in,
                              void* d_out, int out_size) {
    const float* imr     = (const float*)d_in[0];
    const float* pgr     = (const float*)d_in[1];
    const float* nodes   = (const float*)d_in[2];
    const int*   focus   = (const int*)d_in[3];
    const int*   n2g     = (const int*)d_in[4];
    const int*   targets = (const int*)d_in[5];
    const float* feats   = (const float*)d_in[6];
    int p = 7;
    if (p < n_in && in_sizes[p] == 1) p++;  // skip num_graphs_in_batch scalar if present
    const float* dist_table = (const float*)d_in[p++];  // [10]
    const float* no_more    = (const float*)d_in[p++];  // [132]
    const float* sW1 = (const float*)d_in[p++];         // [516,64]
    const float* sb1 = (const float*)d_in[p++];         // [64]
    const float* sW2 = (const float*)d_in[p++];         // [64]
    const float* sb2 = (const float*)d_in[p++];         // [1]
    const float* tW1 = (const float*)d_in[p++];         // [516,64]
    const float* tb1 = (const float*)d_in[p++];         // [64]
    const float* tW2 = (const float*)d_in[p++];         // [64,3]
    const float* tb2 = (const float*)d_in[p++];         // [3]
    float* out = (float*)d_out;

    kP<<<1, 128>>>(dist_table, no_more, sW1, tW1);
    kA<<<G_ / 8, 128>>>(imr, pgr, nodes, focus, sW1, sb1, tW1, tb1, sW2, sb2, out);
    kB<<<N_ / 128, 256>>>(nodes, sW1, tW1, n2g);
    kE<<<1184, 256>>>(targets, (const float4*)feats, sW1, tW1, sW2, sb2, tW2, tb2, out);
}